// round 11
// baseline (speedup 1.0000x reference)
#include <cuda_runtime.h>

// ---------------- problem constants ----------------
#define BV    4      // batch
#define NCAM  6      // cameras
#define DDEP  41     // depth bins
#define FHH   8      // feature H
#define FWW   22     // feature W
#define CC    128    // channels
#define NXX   200
#define NYY   200
#define NPTS  (BV*NCAM*DDEP*FHH*FWW)   // 173184
#define NVOX  (NXX*NYY*BV)             // 160000

#define SCAN_BLOCK   1024
#define NSCAN_BLOCKS ((NVOX + SCAN_BLOCK - 1) / SCAN_BLOCK) // 157

// ---------------- static scratch (no allocations allowed) ----------------
// Invariant: g_count == 0 and g_alloc == 0 at kernel_launch entry.
// (Zero-initialized at load; k_gather restores both at the end of each launch.)
__device__ __align__(16) int g_count[NVOX];  // points per voxel
__device__ __align__(16) int g_off[NVOX];    // FINAL absolute CSR offset
__device__ int   g_alloc;                    // CSR allocation cursor
__device__ int   g_pvox[NPTS];               // voxel id per point (-1 dropped)
__device__ int   g_prank[NPTS];              // rank of point within its voxel
__device__ int   g_idx[NPTS];                // CSR point indices

// strict separately-rounded dot-3 (FROZEN — matches reference bit-exactly)
__device__ __forceinline__ float dot3_strict(float a0, float a1, float a2,
                                             float b0, float b1, float b2) {
    float p0 = __fmul_rn(a0, b0);
    float p1 = __fmul_rn(a1, b1);
    float p2 = __fmul_rn(a2, b2);
    return __fadd_rn(__fadd_rn(p0, p1), p2);
}

// ---------------- 3x3 inverse (FROZEN — R6/R7 verified) ----------------
__device__ void inv3_lu(const float* __restrict__ A, float* __restrict__ X) {
    float a[3][3];
    #pragma unroll
    for (int r = 0; r < 3; r++)
        #pragma unroll
        for (int c = 0; c < 3; c++)
            a[r][c] = A[r*3+c];
    int piv[3] = {0, 1, 2};
    {
        int p = 0;
        float m = fabsf(a[0][0]);
        if (fabsf(a[1][0]) > m) { m = fabsf(a[1][0]); p = 1; }
        if (fabsf(a[2][0]) > m) { p = 2; }
        if (p != 0) {
            #pragma unroll
            for (int c = 0; c < 3; c++) { float t = a[0][c]; a[0][c] = a[p][c]; a[p][c] = t; }
            int t = piv[0]; piv[0] = piv[p]; piv[p] = t;
        }
        float rcp = 1.0f / a[0][0];
        float l10 = __fmul_rn(a[1][0], rcp);
        float l20 = __fmul_rn(a[2][0], rcp);
        a[1][1] = fmaf(-l10, a[0][1], a[1][1]);
        a[1][2] = fmaf(-l10, a[0][2], a[1][2]);
        a[2][1] = fmaf(-l20, a[0][1], a[2][1]);
        a[2][2] = fmaf(-l20, a[0][2], a[2][2]);
        a[1][0] = l10; a[2][0] = l20;
    }
    {
        if (fabsf(a[2][1]) > fabsf(a[1][1])) {
            #pragma unroll
            for (int c = 0; c < 3; c++) { float t = a[1][c]; a[1][c] = a[2][c]; a[2][c] = t; }
            int t = piv[1]; piv[1] = piv[2]; piv[2] = t;
        }
        float rcp = 1.0f / a[1][1];
        float l21 = __fmul_rn(a[2][1], rcp);
        a[2][2] = fmaf(-l21, a[1][2], a[2][2]);
        a[2][1] = l21;
    }
    float r00 = 1.0f / a[0][0];
    float r11 = 1.0f / a[1][1];
    float r22 = 1.0f / a[2][2];
    #pragma unroll
    for (int c = 0; c < 3; c++) {
        float b0 = (piv[0] == c) ? 1.0f : 0.0f;
        float b1 = (piv[1] == c) ? 1.0f : 0.0f;
        float b2 = (piv[2] == c) ? 1.0f : 0.0f;
        float y0 = b0;
        float y1 = fmaf(-a[1][0], y0, b1);
        float y2 = fmaf(-a[2][1], y1, fmaf(-a[2][0], y0, b2));
        float x2 = __fmul_rn(y2, r22);
        float x1 = __fmul_rn(fmaf(-a[1][2], x2, y1), r11);
        float x0 = __fmul_rn(fmaf(-a[0][1], x1, fmaf(-a[0][2], x2, y0)), r00);
        X[0*3+c] = x0; X[1*3+c] = x1; X[2*3+c] = x2;
    }
}

// ---------------- K0: geometry (FROZEN) + count/rank; cams folded in-block ----
__global__ __launch_bounds__(256) void k_geom(const float* __restrict__ rots,
                                              const float* __restrict__ trans,
                                              const float* __restrict__ intrins,
                                              const float* __restrict__ post_rots,
                                              const float* __restrict__ post_trans) {
    // per-cam: Pinv[9], post_trans[3], combine[9], trans[3]
    __shared__ float scam[BV*NCAM][24];
    int tid = threadIdx.x;
    if (tid < BV*NCAM) {
        int c = tid;
        float P[9], Ki[9];
        inv3_lu(post_rots + c*9, P);
        inv3_lu(intrins  + c*9, Ki);
        const float* R  = rots + c*9;
        float* cm = scam[c];
        #pragma unroll
        for (int r = 0; r < 9; r++) cm[r] = P[r];
        #pragma unroll
        for (int r = 0; r < 3; r++) cm[9+r] = post_trans[c*3+r];
        #pragma unroll
        for (int r = 0; r < 3; r++)
            #pragma unroll
            for (int cc2 = 0; cc2 < 3; cc2++)
                cm[12 + r*3 + cc2] = dot3_strict(R[r*3+0], R[r*3+1], R[r*3+2],
                                                 Ki[0*3+cc2], Ki[1*3+cc2], Ki[2*3+cc2]);
        #pragma unroll
        for (int r = 0; r < 3; r++) cm[21+r] = trans[c*3+r];
    }
    __syncthreads();

    int p = blockIdx.x * blockDim.x + tid;
    if (p >= NPTS) return;

    int w = p % FWW;
    int t = p / FWW;
    int h = t % FHH;  t /= FHH;
    int d = t % DDEP;
    int cam = t / DDEP;            // b*NCAM + n
    int b   = cam / NCAM;

    // linspace WITHOUT endpoint fixup (verified bit-exact in R7)
    const float stepx = 351.0f / 21.0f;
    const float stepy = 127.0f / 7.0f;
    float fx = __fmul_rn((float)w, stepx);
    float fy = __fmul_rn((float)h, stepy);
    float fd = 4.0f + (float)d;

    const float* cm = scam[cam];

    float s0 = __fadd_rn(fx, -cm[9]);
    float s1 = __fadd_rn(fy, -cm[10]);
    float s2 = __fadd_rn(fd, -cm[11]);

    float p2x = dot3_strict(cm[0], cm[1], cm[2], s0, s1, s2);
    float p2y = dot3_strict(cm[3], cm[4], cm[5], s0, s1, s2);
    float p2z = dot3_strict(cm[6], cm[7], cm[8], s0, s1, s2);

    float p3x = __fmul_rn(p2x, p2z);
    float p3y = __fmul_rn(p2y, p2z);
    float p3z = p2z;

    float ex = __fadd_rn(dot3_strict(cm[12], cm[13], cm[14], p3x, p3y, p3z), cm[21]);
    float ey = __fadd_rn(dot3_strict(cm[15], cm[16], cm[17], p3x, p3y, p3z), cm[22]);
    float ez = __fadd_rn(dot3_strict(cm[18], cm[19], cm[20], p3x, p3y, p3z), cm[23]);

    float vx = __fadd_rn(ex, 50.0f) / 0.5f;
    float vy = __fadd_rn(ey, 50.0f) / 0.5f;
    float vz = __fdiv_rn(__fadd_rn(ez, 10.0f), 20.0f);
    int gx = (int)vx;
    int gy = (int)vy;
    int gz = (int)vz;

    int vox = -1, rank = 0;
    if (gx >= 0 && gx < NXX && gy >= 0 && gy < NYY && gz == 0) {
        vox = (gx * NYY + gy) * BV + b;
        rank = atomicAdd(&g_count[vox], 1);
    }
    g_pvox[p]  = vox;
    g_prank[p] = rank;
}

// ---------------- K1: block-local scan + atomic base allocation ----------------
// Writes FINAL absolute offsets to g_off. Block bases come from atomicAdd on
// g_alloc (placement order varies run-to-run; per-voxel list content/order do
// not, so output bits are unaffected).
__global__ __launch_bounds__(256) void k_scan1() {
    __shared__ int wsum[8];
    __shared__ int sbase;
    int bb = blockIdx.x, t = threadIdx.x;
    int lane = t & 31, wid = t >> 5;
    int base = bb * SCAN_BLOCK + t * 4;

    int v0 = 0, v1 = 0, v2 = 0, v3 = 0;
    if (base + 3 < NVOX) {
        int4 q = *reinterpret_cast<const int4*>(&g_count[base]);
        v0 = q.x; v1 = q.y; v2 = q.z; v3 = q.w;
    } else {
        if (base     < NVOX) v0 = g_count[base];
        if (base + 1 < NVOX) v1 = g_count[base + 1];
        if (base + 2 < NVOX) v2 = g_count[base + 2];
        if (base + 3 < NVOX) v3 = g_count[base + 3];
    }
    int s = v0 + v1 + v2 + v3;

    int incl = s;
    #pragma unroll
    for (int o = 1; o < 32; o <<= 1) {
        int x = __shfl_up_sync(0xffffffffu, incl, o);
        if (lane >= o) incl += x;
    }
    if (lane == 31) wsum[wid] = incl;
    __syncthreads();
    if (t < 8) {
        int w = wsum[t];
        int iw = w;
        #pragma unroll
        for (int o = 1; o < 8; o <<= 1) {
            int x = __shfl_up_sync(0xffu, iw, o);
            if (t >= o) iw += x;
        }
        wsum[t] = iw - w;     // exclusive warp base
    }
    __syncthreads();

    int excl = incl - s + wsum[wid];
    if (t == 255) sbase = atomicAdd(&g_alloc, excl + s);  // block total
    __syncthreads();

    int run = excl + sbase;
    if (base     < NVOX) { g_off[base]     = run; run += v0; }
    if (base + 1 < NVOX) { g_off[base + 1] = run; run += v1; }
    if (base + 2 < NVOX) { g_off[base + 2] = run; run += v2; }
    if (base + 3 < NVOX) { g_off[base + 3] = run; }
}

// ---------------- K2: fill CSR index array ----------------
__global__ void k_fill() {
    int p = blockIdx.x * blockDim.x + threadIdx.x;
    if (p >= NPTS) return;
    int vox = g_pvox[p];
    if (vox >= 0)
        g_idx[g_off[vox] + g_prank[p]] = p;
}

// ---------------- K3: warp-per-voxel CSR gather; restores scratch state ------
__global__ __launch_bounds__(512) void k_gather(const float* __restrict__ feats,
                                                float* __restrict__ out) {
    __shared__ float tile[32][129];
    __shared__ int s_next;
    int tid  = threadIdx.x;
    int lane = tid & 31;
    int ytile = blockIdx.x, x = blockIdx.y, b = blockIdx.z;
    int ybase = ytile * 32;

    if (tid == 0) {
        s_next = 0;
        if (ytile == 0 && x == 0 && b == 0) g_alloc = 0;   // restore for next launch
    }
    __syncthreads();

    while (true) {
        int v;
        if (lane == 0) v = atomicAdd(&s_next, 1);
        v = __shfl_sync(0xffffffffu, v, 0);
        if (v >= 32) break;
        int y = ybase + v;

        float4 acc = make_float4(0.f, 0.f, 0.f, 0.f);
        if (y < NYY) {
            int vox = (x * NYY + y) * BV + b;
            int cnt = g_count[vox];
            if (lane == 0) g_count[vox] = 0;               // restore for next launch
            if (cnt > 0) {
                const int* idx = g_idx + g_off[vox];
                int j = 0;
                for (; j + 3 < cnt; j += 4) {
                    int p0 = idx[j], p1 = idx[j+1], p2 = idx[j+2], p3 = idx[j+3];
                    float4 a = __ldcs(reinterpret_cast<const float4*>(feats + (size_t)p0 * CC) + lane);
                    float4 c = __ldcs(reinterpret_cast<const float4*>(feats + (size_t)p1 * CC) + lane);
                    float4 e = __ldcs(reinterpret_cast<const float4*>(feats + (size_t)p2 * CC) + lane);
                    float4 f = __ldcs(reinterpret_cast<const float4*>(feats + (size_t)p3 * CC) + lane);
                    acc.x += a.x + c.x; acc.y += a.y + c.y;
                    acc.z += a.z + c.z; acc.w += a.w + c.w;
                    acc.x += e.x + f.x; acc.y += e.y + f.y;
                    acc.z += e.z + f.z; acc.w += e.w + f.w;
                }
                for (; j < cnt; j++) {
                    float4 a = __ldcs(reinterpret_cast<const float4*>(feats + (size_t)idx[j] * CC) + lane);
                    acc.x += a.x; acc.y += a.y; acc.z += a.z; acc.w += a.w;
                }
            }
        }
        tile[v][lane*4 + 0] = acc.x;
        tile[v][lane*4 + 1] = acc.y;
        tile[v][lane*4 + 2] = acc.z;
        tile[v][lane*4 + 3] = acc.w;
    }
    __syncthreads();

    // out[b][c][x][y]: warp = 32 consecutive y for one c -> 128B coalesced, streaming
    #pragma unroll
    for (int k = 0; k < 8; k++) {
        int i2 = tid + k * 512;
        int c  = i2 >> 5;
        int yy = i2 & 31;
        int y  = ybase + yy;
        if (y < NYY)
            __stcs(&out[((size_t)(b * CC + c) * NXX + x) * NYY + y], tile[yy][c]);
    }
}

// ---------------- launch ----------------
extern "C" void kernel_launch(void* const* d_in, const int* in_sizes, int n_in,
                              void* d_out, int out_size) {
    const float* cam_feats  = (const float*)d_in[0];
    const float* rots       = (const float*)d_in[1];
    const float* trans      = (const float*)d_in[2];
    const float* intrins    = (const float*)d_in[3];
    const float* post_rots  = (const float*)d_in[4];
    const float* post_trans = (const float*)d_in[5];
    float* out = (float*)d_out;

    k_geom<<<(NPTS + 255) / 256, 256>>>(rots, trans, intrins, post_rots, post_trans);
    k_scan1<<<NSCAN_BLOCKS, 256>>>();
    k_fill<<<(NPTS + 255) / 256, 256>>>();

    dim3 ggrid((NYY + 31) / 32, NXX, BV);
    k_gather<<<ggrid, 512>>>(cam_feats, out);
}

// round 12
// speedup vs baseline: 2.5428x; 2.5428x over previous
#include <cuda_runtime.h>

// ---------------- problem constants ----------------
#define BV    4      // batch
#define NCAM  6      // cameras
#define DDEP  41     // depth bins
#define FHH   8      // feature H
#define FWW   22     // feature W
#define CC    128    // channels
#define NXX   200
#define NYY   200
#define NPTS  (BV*NCAM*DDEP*FHH*FWW)   // 173184
#define NVOX  (NXX*NYY*BV)             // 160000 (divisible by 4)

#define SCAN_BLOCK   1024
#define NSCAN_BLOCKS ((NVOX + SCAN_BLOCK - 1) / SCAN_BLOCK) // 157

// ---------------- static scratch (no allocations allowed) ----------------
// Replay invariants at kernel_launch entry: g_count == 0, g_alloc == 0.
// (Load-time zero-init; k_scan1 re-zeroes g_count, k_fill re-zeroes g_alloc.)
__device__ __align__(16) int g_count[NVOX];  // points per voxel (transient)
__device__ __align__(16) int g_cnt2[NVOX];   // read-only copy for gather
__device__ __align__(16) int g_off[NVOX];    // FINAL absolute CSR offset
__device__ int   g_alloc;                    // CSR allocation cursor
__device__ int   g_pvox[NPTS];               // voxel id per point (-1 dropped)
__device__ int   g_prank[NPTS];              // rank of point within its voxel
__device__ int   g_idx[NPTS];                // CSR point indices

// strict separately-rounded dot-3 (FROZEN — matches reference bit-exactly)
__device__ __forceinline__ float dot3_strict(float a0, float a1, float a2,
                                             float b0, float b1, float b2) {
    float p0 = __fmul_rn(a0, b0);
    float p1 = __fmul_rn(a1, b1);
    float p2 = __fmul_rn(a2, b2);
    return __fadd_rn(__fadd_rn(p0, p1), p2);
}

// ---------------- 3x3 inverse (FROZEN — R6/R7 verified) ----------------
__device__ void inv3_lu(const float* __restrict__ A, float* __restrict__ X) {
    float a[3][3];
    #pragma unroll
    for (int r = 0; r < 3; r++)
        #pragma unroll
        for (int c = 0; c < 3; c++)
            a[r][c] = A[r*3+c];
    int piv[3] = {0, 1, 2};
    {
        int p = 0;
        float m = fabsf(a[0][0]);
        if (fabsf(a[1][0]) > m) { m = fabsf(a[1][0]); p = 1; }
        if (fabsf(a[2][0]) > m) { p = 2; }
        if (p != 0) {
            #pragma unroll
            for (int c = 0; c < 3; c++) { float t = a[0][c]; a[0][c] = a[p][c]; a[p][c] = t; }
            int t = piv[0]; piv[0] = piv[p]; piv[p] = t;
        }
        float rcp = 1.0f / a[0][0];
        float l10 = __fmul_rn(a[1][0], rcp);
        float l20 = __fmul_rn(a[2][0], rcp);
        a[1][1] = fmaf(-l10, a[0][1], a[1][1]);
        a[1][2] = fmaf(-l10, a[0][2], a[1][2]);
        a[2][1] = fmaf(-l20, a[0][1], a[2][1]);
        a[2][2] = fmaf(-l20, a[0][2], a[2][2]);
        a[1][0] = l10; a[2][0] = l20;
    }
    {
        if (fabsf(a[2][1]) > fabsf(a[1][1])) {
            #pragma unroll
            for (int c = 0; c < 3; c++) { float t = a[1][c]; a[1][c] = a[2][c]; a[2][c] = t; }
            int t = piv[1]; piv[1] = piv[2]; piv[2] = t;
        }
        float rcp = 1.0f / a[1][1];
        float l21 = __fmul_rn(a[2][1], rcp);
        a[2][2] = fmaf(-l21, a[1][2], a[2][2]);
        a[2][1] = l21;
    }
    float r00 = 1.0f / a[0][0];
    float r11 = 1.0f / a[1][1];
    float r22 = 1.0f / a[2][2];
    #pragma unroll
    for (int c = 0; c < 3; c++) {
        float b0 = (piv[0] == c) ? 1.0f : 0.0f;
        float b1 = (piv[1] == c) ? 1.0f : 0.0f;
        float b2 = (piv[2] == c) ? 1.0f : 0.0f;
        float y0 = b0;
        float y1 = fmaf(-a[1][0], y0, b1);
        float y2 = fmaf(-a[2][1], y1, fmaf(-a[2][0], y0, b2));
        float x2 = __fmul_rn(y2, r22);
        float x1 = __fmul_rn(fmaf(-a[1][2], x2, y1), r11);
        float x0 = __fmul_rn(fmaf(-a[0][1], x1, fmaf(-a[0][2], x2, y0)), r00);
        X[0*3+c] = x0; X[1*3+c] = x1; X[2*3+c] = x2;
    }
}

// ---------------- K0: geometry (FROZEN) + count/rank; cams folded in-block ----
__global__ __launch_bounds__(256) void k_geom(const float* __restrict__ rots,
                                              const float* __restrict__ trans,
                                              const float* __restrict__ intrins,
                                              const float* __restrict__ post_rots,
                                              const float* __restrict__ post_trans) {
    // per-cam: Pinv[9], post_trans[3], combine[9], trans[3]
    __shared__ float scam[BV*NCAM][24];
    int tid = threadIdx.x;
    if (tid < BV*NCAM) {
        int c = tid;
        float P[9], Ki[9];
        inv3_lu(post_rots + c*9, P);
        inv3_lu(intrins  + c*9, Ki);
        const float* R  = rots + c*9;
        float* cm = scam[c];
        #pragma unroll
        for (int r = 0; r < 9; r++) cm[r] = P[r];
        #pragma unroll
        for (int r = 0; r < 3; r++) cm[9+r] = post_trans[c*3+r];
        #pragma unroll
        for (int r = 0; r < 3; r++)
            #pragma unroll
            for (int cc2 = 0; cc2 < 3; cc2++)
                cm[12 + r*3 + cc2] = dot3_strict(R[r*3+0], R[r*3+1], R[r*3+2],
                                                 Ki[0*3+cc2], Ki[1*3+cc2], Ki[2*3+cc2]);
        #pragma unroll
        for (int r = 0; r < 3; r++) cm[21+r] = trans[c*3+r];
    }
    __syncthreads();

    int p = blockIdx.x * blockDim.x + tid;
    if (p >= NPTS) return;

    int w = p % FWW;
    int t = p / FWW;
    int h = t % FHH;  t /= FHH;
    int d = t % DDEP;
    int cam = t / DDEP;            // b*NCAM + n
    int b   = cam / NCAM;

    // linspace WITHOUT endpoint fixup (verified bit-exact in R7)
    const float stepx = 351.0f / 21.0f;
    const float stepy = 127.0f / 7.0f;
    float fx = __fmul_rn((float)w, stepx);
    float fy = __fmul_rn((float)h, stepy);
    float fd = 4.0f + (float)d;

    const float* cm = scam[cam];

    float s0 = __fadd_rn(fx, -cm[9]);
    float s1 = __fadd_rn(fy, -cm[10]);
    float s2 = __fadd_rn(fd, -cm[11]);

    float p2x = dot3_strict(cm[0], cm[1], cm[2], s0, s1, s2);
    float p2y = dot3_strict(cm[3], cm[4], cm[5], s0, s1, s2);
    float p2z = dot3_strict(cm[6], cm[7], cm[8], s0, s1, s2);

    float p3x = __fmul_rn(p2x, p2z);
    float p3y = __fmul_rn(p2y, p2z);
    float p3z = p2z;

    float ex = __fadd_rn(dot3_strict(cm[12], cm[13], cm[14], p3x, p3y, p3z), cm[21]);
    float ey = __fadd_rn(dot3_strict(cm[15], cm[16], cm[17], p3x, p3y, p3z), cm[22]);
    float ez = __fadd_rn(dot3_strict(cm[18], cm[19], cm[20], p3x, p3y, p3z), cm[23]);

    float vx = __fadd_rn(ex, 50.0f) / 0.5f;
    float vy = __fadd_rn(ey, 50.0f) / 0.5f;
    float vz = __fdiv_rn(__fadd_rn(ez, 10.0f), 20.0f);
    int gx = (int)vx;
    int gy = (int)vy;
    int gz = (int)vz;

    int vox = -1, rank = 0;
    if (gx >= 0 && gx < NXX && gy >= 0 && gy < NYY && gz == 0) {
        vox = (gx * NYY + gy) * BV + b;
        rank = atomicAdd(&g_count[vox], 1);
    }
    g_pvox[p]  = vox;
    g_prank[p] = rank;
}

// ---------------- K1: block scan + atomic base; copy counts; zero g_count ----
// Placement order varies run-to-run (atomic base), but per-voxel list content
// and order do not, so output bits are unaffected.
__global__ __launch_bounds__(256) void k_scan1() {
    __shared__ int wsum[8];
    __shared__ int sbase;
    int bb = blockIdx.x, t = threadIdx.x;
    int lane = t & 31, wid = t >> 5;
    int base = bb * SCAN_BLOCK + t * 4;   // NVOX%4==0: int4-clean

    int4 q = make_int4(0, 0, 0, 0);
    if (base < NVOX) q = *reinterpret_cast<const int4*>(&g_count[base]);
    int s = q.x + q.y + q.z + q.w;

    int incl = s;
    #pragma unroll
    for (int o = 1; o < 32; o <<= 1) {
        int x = __shfl_up_sync(0xffffffffu, incl, o);
        if (lane >= o) incl += x;
    }
    if (lane == 31) wsum[wid] = incl;
    __syncthreads();
    if (t < 8) {
        int w = wsum[t];
        int iw = w;
        #pragma unroll
        for (int o = 1; o < 8; o <<= 1) {
            int x = __shfl_up_sync(0xffu, iw, o);
            if (t >= o) iw += x;
        }
        wsum[t] = iw - w;     // exclusive warp base
    }
    __syncthreads();

    int excl = incl - s + wsum[wid];
    if (t == 255) sbase = atomicAdd(&g_alloc, excl + s);  // block total
    __syncthreads();

    if (base < NVOX) {
        int r0 = excl + sbase;
        int r1 = r0 + q.x;
        int r2 = r1 + q.y;
        int r3 = r2 + q.z;
        *reinterpret_cast<int4*>(&g_off[base])  = make_int4(r0, r1, r2, r3);
        *reinterpret_cast<int4*>(&g_cnt2[base]) = q;                       // RO copy
        *reinterpret_cast<int4*>(&g_count[base]) = make_int4(0, 0, 0, 0); // reset
    }
}

// ---------------- K2: fill CSR index array; reset alloc cursor ----------------
__global__ void k_fill() {
    int p = blockIdx.x * blockDim.x + threadIdx.x;
    if (p == 0) g_alloc = 0;            // consumed by scan1 already; reset for next launch
    if (p >= NPTS) return;
    int vox = g_pvox[p];
    if (vox >= 0)
        g_idx[g_off[vox] + g_prank[p]] = p;
}

// ---------------- K3: warp-per-voxel CSR gather (PURE READ + out stores) ------
__global__ __launch_bounds__(512) void k_gather(const float* __restrict__ feats,
                                                float* __restrict__ out) {
    __shared__ float tile[32][129];
    __shared__ int s_next;
    int tid  = threadIdx.x;
    int lane = tid & 31;
    int ytile = blockIdx.x, x = blockIdx.y, b = blockIdx.z;
    int ybase = ytile * 32;

    if (tid == 0) s_next = 0;
    __syncthreads();

    while (true) {
        int v;
        if (lane == 0) v = atomicAdd(&s_next, 1);
        v = __shfl_sync(0xffffffffu, v, 0);
        if (v >= 32) break;
        int y = ybase + v;

        float4 acc = make_float4(0.f, 0.f, 0.f, 0.f);
        if (y < NYY) {
            int vox = (x * NYY + y) * BV + b;
            int cnt = g_cnt2[vox];
            if (cnt > 0) {
                const int* idx = g_idx + g_off[vox];
                int j = 0;
                for (; j + 3 < cnt; j += 4) {
                    int p0 = idx[j], p1 = idx[j+1], p2 = idx[j+2], p3 = idx[j+3];
                    float4 a = __ldcs(reinterpret_cast<const float4*>(feats + (size_t)p0 * CC) + lane);
                    float4 c = __ldcs(reinterpret_cast<const float4*>(feats + (size_t)p1 * CC) + lane);
                    float4 e = __ldcs(reinterpret_cast<const float4*>(feats + (size_t)p2 * CC) + lane);
                    float4 f = __ldcs(reinterpret_cast<const float4*>(feats + (size_t)p3 * CC) + lane);
                    acc.x += a.x + c.x; acc.y += a.y + c.y;
                    acc.z += a.z + c.z; acc.w += a.w + c.w;
                    acc.x += e.x + f.x; acc.y += e.y + f.y;
                    acc.z += e.z + f.z; acc.w += e.w + f.w;
                }
                for (; j < cnt; j++) {
                    float4 a = __ldcs(reinterpret_cast<const float4*>(feats + (size_t)idx[j] * CC) + lane);
                    acc.x += a.x; acc.y += a.y; acc.z += a.z; acc.w += a.w;
                }
            }
        }
        tile[v][lane*4 + 0] = acc.x;
        tile[v][lane*4 + 1] = acc.y;
        tile[v][lane*4 + 2] = acc.z;
        tile[v][lane*4 + 3] = acc.w;
    }
    __syncthreads();

    // out[b][c][x][y]: warp = 32 consecutive y for one c -> 128B coalesced, streaming
    #pragma unroll
    for (int k = 0; k < 8; k++) {
        int i2 = tid + k * 512;
        int c  = i2 >> 5;
        int yy = i2 & 31;
        int y  = ybase + yy;
        if (y < NYY)
            __stcs(&out[((size_t)(b * CC + c) * NXX + x) * NYY + y], tile[yy][c]);
    }
}

// ---------------- launch ----------------
extern "C" void kernel_launch(void* const* d_in, const int* in_sizes, int n_in,
                              void* d_out, int out_size) {
    const float* cam_feats  = (const float*)d_in[0];
    const float* rots       = (const float*)d_in[1];
    const float* trans      = (const float*)d_in[2];
    const float* intrins    = (const float*)d_in[3];
    const float* post_rots  = (const float*)d_in[4];
    const float* post_trans = (const float*)d_in[5];
    float* out = (float*)d_out;

    k_geom<<<(NPTS + 255) / 256, 256>>>(rots, trans, intrins, post_rots, post_trans);
    k_scan1<<<NSCAN_BLOCKS, 256>>>();
    k_fill<<<(NPTS + 255) / 256, 256>>>();

    dim3 ggrid((NYY + 31) / 32, NXX, BV);
    k_gather<<<ggrid, 512>>>(cam_feats, out);
}

// round 13
// speedup vs baseline: 2.6860x; 1.0563x over previous
#include <cuda_runtime.h>

// ---------------- problem constants ----------------
#define BV    4      // batch
#define NCAM  6      // cameras
#define DDEP  41     // depth bins
#define FHH   8      // feature H
#define FWW   22     // feature W
#define CC    128    // channels
#define NXX   200
#define NYY   200
#define NPTS  (BV*NCAM*DDEP*FHH*FWW)   // 173184
#define NVOX  (NXX*NYY*BV)             // 160000 (divisible by 4)

#define SCAN_BLOCK   1024
#define NSCAN_BLOCKS ((NVOX + SCAN_BLOCK - 1) / SCAN_BLOCK) // 157

// ---------------- static scratch (no allocations allowed) ----------------
// Replay invariants at kernel_launch entry: g_count == 0, g_alloc == 0.
__device__ __align__(16) int  g_count[NVOX];   // points per voxel (transient)
__device__ __align__(16) int2 g_meta[NVOX];    // {final CSR offset, count} (RO in gather)
__device__ int   g_alloc;                      // CSR allocation cursor
__device__ int   g_pvox[NPTS];                 // voxel id per point (-1 dropped)
__device__ int   g_prank[NPTS];                // rank of point within its voxel
__device__ int   g_idx[NPTS];                  // CSR point indices

// strict separately-rounded dot-3 (FROZEN — matches reference bit-exactly)
__device__ __forceinline__ float dot3_strict(float a0, float a1, float a2,
                                             float b0, float b1, float b2) {
    float p0 = __fmul_rn(a0, b0);
    float p1 = __fmul_rn(a1, b1);
    float p2 = __fmul_rn(a2, b2);
    return __fadd_rn(__fadd_rn(p0, p1), p2);
}

// ---------------- 3x3 inverse (FROZEN — R6/R7 verified) ----------------
__device__ void inv3_lu(const float* __restrict__ A, float* __restrict__ X) {
    float a[3][3];
    #pragma unroll
    for (int r = 0; r < 3; r++)
        #pragma unroll
        for (int c = 0; c < 3; c++)
            a[r][c] = A[r*3+c];
    int piv[3] = {0, 1, 2};
    {
        int p = 0;
        float m = fabsf(a[0][0]);
        if (fabsf(a[1][0]) > m) { m = fabsf(a[1][0]); p = 1; }
        if (fabsf(a[2][0]) > m) { p = 2; }
        if (p != 0) {
            #pragma unroll
            for (int c = 0; c < 3; c++) { float t = a[0][c]; a[0][c] = a[p][c]; a[p][c] = t; }
            int t = piv[0]; piv[0] = piv[p]; piv[p] = t;
        }
        float rcp = 1.0f / a[0][0];
        float l10 = __fmul_rn(a[1][0], rcp);
        float l20 = __fmul_rn(a[2][0], rcp);
        a[1][1] = fmaf(-l10, a[0][1], a[1][1]);
        a[1][2] = fmaf(-l10, a[0][2], a[1][2]);
        a[2][1] = fmaf(-l20, a[0][1], a[2][1]);
        a[2][2] = fmaf(-l20, a[0][2], a[2][2]);
        a[1][0] = l10; a[2][0] = l20;
    }
    {
        if (fabsf(a[2][1]) > fabsf(a[1][1])) {
            #pragma unroll
            for (int c = 0; c < 3; c++) { float t = a[1][c]; a[1][c] = a[2][c]; a[2][c] = t; }
            int t = piv[1]; piv[1] = piv[2]; piv[2] = t;
        }
        float rcp = 1.0f / a[1][1];
        float l21 = __fmul_rn(a[2][1], rcp);
        a[2][2] = fmaf(-l21, a[1][2], a[2][2]);
        a[2][1] = l21;
    }
    float r00 = 1.0f / a[0][0];
    float r11 = 1.0f / a[1][1];
    float r22 = 1.0f / a[2][2];
    #pragma unroll
    for (int c = 0; c < 3; c++) {
        float b0 = (piv[0] == c) ? 1.0f : 0.0f;
        float b1 = (piv[1] == c) ? 1.0f : 0.0f;
        float b2 = (piv[2] == c) ? 1.0f : 0.0f;
        float y0 = b0;
        float y1 = fmaf(-a[1][0], y0, b1);
        float y2 = fmaf(-a[2][1], y1, fmaf(-a[2][0], y0, b2));
        float x2 = __fmul_rn(y2, r22);
        float x1 = __fmul_rn(fmaf(-a[1][2], x2, y1), r11);
        float x0 = __fmul_rn(fmaf(-a[0][1], x1, fmaf(-a[0][2], x2, y0)), r00);
        X[0*3+c] = x0; X[1*3+c] = x1; X[2*3+c] = x2;
    }
}

// ---------------- K0: geometry (FROZEN) + count/rank; cams folded in-block ----
__global__ __launch_bounds__(256) void k_geom(const float* __restrict__ rots,
                                              const float* __restrict__ trans,
                                              const float* __restrict__ intrins,
                                              const float* __restrict__ post_rots,
                                              const float* __restrict__ post_trans) {
    __shared__ float scam[BV*NCAM][24];
    int tid = threadIdx.x;
    if (tid < BV*NCAM) {
        int c = tid;
        float P[9], Ki[9];
        inv3_lu(post_rots + c*9, P);
        inv3_lu(intrins  + c*9, Ki);
        const float* R  = rots + c*9;
        float* cm = scam[c];
        #pragma unroll
        for (int r = 0; r < 9; r++) cm[r] = P[r];
        #pragma unroll
        for (int r = 0; r < 3; r++) cm[9+r] = post_trans[c*3+r];
        #pragma unroll
        for (int r = 0; r < 3; r++)
            #pragma unroll
            for (int cc2 = 0; cc2 < 3; cc2++)
                cm[12 + r*3 + cc2] = dot3_strict(R[r*3+0], R[r*3+1], R[r*3+2],
                                                 Ki[0*3+cc2], Ki[1*3+cc2], Ki[2*3+cc2]);
        #pragma unroll
        for (int r = 0; r < 3; r++) cm[21+r] = trans[c*3+r];
    }
    __syncthreads();

    int p = blockIdx.x * blockDim.x + tid;
    if (p >= NPTS) return;

    int w = p % FWW;
    int t = p / FWW;
    int h = t % FHH;  t /= FHH;
    int d = t % DDEP;
    int cam = t / DDEP;            // b*NCAM + n
    int b   = cam / NCAM;

    // linspace WITHOUT endpoint fixup (verified bit-exact in R7)
    const float stepx = 351.0f / 21.0f;
    const float stepy = 127.0f / 7.0f;
    float fx = __fmul_rn((float)w, stepx);
    float fy = __fmul_rn((float)h, stepy);
    float fd = 4.0f + (float)d;

    const float* cm = scam[cam];

    float s0 = __fadd_rn(fx, -cm[9]);
    float s1 = __fadd_rn(fy, -cm[10]);
    float s2 = __fadd_rn(fd, -cm[11]);

    float p2x = dot3_strict(cm[0], cm[1], cm[2], s0, s1, s2);
    float p2y = dot3_strict(cm[3], cm[4], cm[5], s0, s1, s2);
    float p2z = dot3_strict(cm[6], cm[7], cm[8], s0, s1, s2);

    float p3x = __fmul_rn(p2x, p2z);
    float p3y = __fmul_rn(p2y, p2z);
    float p3z = p2z;

    float ex = __fadd_rn(dot3_strict(cm[12], cm[13], cm[14], p3x, p3y, p3z), cm[21]);
    float ey = __fadd_rn(dot3_strict(cm[15], cm[16], cm[17], p3x, p3y, p3z), cm[22]);
    float ez = __fadd_rn(dot3_strict(cm[18], cm[19], cm[20], p3x, p3y, p3z), cm[23]);

    float vx = __fadd_rn(ex, 50.0f) / 0.5f;
    float vy = __fadd_rn(ey, 50.0f) / 0.5f;
    float vz = __fdiv_rn(__fadd_rn(ez, 10.0f), 20.0f);
    int gx = (int)vx;
    int gy = (int)vy;
    int gz = (int)vz;

    int vox = -1, rank = 0;
    if (gx >= 0 && gx < NXX && gy >= 0 && gy < NYY && gz == 0) {
        vox = (gx * NYY + gy) * BV + b;
        rank = atomicAdd(&g_count[vox], 1);
    }
    g_pvox[p]  = vox;
    g_prank[p] = rank;
}

// ---------------- K1: block scan + atomic base; emit {off,cnt}; zero g_count --
__global__ __launch_bounds__(256) void k_scan1() {
    __shared__ int wsum[8];
    __shared__ int sbase;
    int bb = blockIdx.x, t = threadIdx.x;
    int lane = t & 31, wid = t >> 5;
    int base = bb * SCAN_BLOCK + t * 4;   // NVOX%4==0: int4-clean

    int4 q = make_int4(0, 0, 0, 0);
    if (base < NVOX) q = *reinterpret_cast<const int4*>(&g_count[base]);
    int s = q.x + q.y + q.z + q.w;

    int incl = s;
    #pragma unroll
    for (int o = 1; o < 32; o <<= 1) {
        int x = __shfl_up_sync(0xffffffffu, incl, o);
        if (lane >= o) incl += x;
    }
    if (lane == 31) wsum[wid] = incl;
    __syncthreads();
    if (t < 8) {
        int w = wsum[t];
        int iw = w;
        #pragma unroll
        for (int o = 1; o < 8; o <<= 1) {
            int x = __shfl_up_sync(0xffu, iw, o);
            if (t >= o) iw += x;
        }
        wsum[t] = iw - w;     // exclusive warp base
    }
    __syncthreads();

    int excl = incl - s + wsum[wid];
    if (t == 255) sbase = atomicAdd(&g_alloc, excl + s);  // block total
    __syncthreads();

    if (base < NVOX) {
        int r0 = excl + sbase;
        int r1 = r0 + q.x;
        int r2 = r1 + q.y;
        int r3 = r2 + q.z;
        int4* mp = reinterpret_cast<int4*>(&g_meta[base]);
        mp[0] = make_int4(r0, q.x, r1, q.y);
        mp[1] = make_int4(r2, q.z, r3, q.w);
        *reinterpret_cast<int4*>(&g_count[base]) = make_int4(0, 0, 0, 0); // reset
    }
}

// ---------------- K2: fill CSR index array; reset alloc cursor ----------------
__global__ void k_fill() {
    int p = blockIdx.x * blockDim.x + threadIdx.x;
    if (p == 0) g_alloc = 0;            // reset for next launch
    if (p >= NPTS) return;
    int vox = g_pvox[p];
    if (vox >= 0)
        g_idx[g_meta[vox].x + g_prank[p]] = p;
}

// ---------------- K3: ballot-dispatched warp-per-voxel gather (pure read) -----
// block: 512 threads (16 warps); grid (7 ytiles, NX, B).
__global__ __launch_bounds__(512) void k_gather(const float* __restrict__ feats,
                                                float* __restrict__ out) {
    __shared__ float tile[32][132];     // rows float4-aligned (132*4 % 16 == 0)
    int tid  = threadIdx.x;
    int lane = tid & 31;
    int wid  = tid >> 5;
    int ytile = blockIdx.x, x = blockIdx.y, b = blockIdx.z;
    int ybase = ytile * 32;

    // zero the tile (empty voxels output zeros)
    {
        float4 z = make_float4(0.f, 0.f, 0.f, 0.f);
        float4* tp = reinterpret_cast<float4*>(&tile[0][0]);
        #pragma unroll
        for (int k = 0; k < 3; k++) {
            int i = tid + k * 512;
            if (i < 32 * 33) tp[i] = z;    // 32*132/4 = 1056
        }
    }

    // lane-parallel metadata: lane v covers y = ybase + v
    int vy = ybase + lane;
    int2 md = make_int2(0, 0);
    if (vy < NYY) md = g_meta[(x * NYY + vy) * BV + b];
    unsigned mask = __ballot_sync(0xffffffffu, md.y != 0);
    __syncthreads();   // tile zeroing done before any accumulation store

    // round-robin occupied voxels over 16 warps
    unsigned m = mask;
    int i = 0;
    while (m) {
        int v = __ffs(m) - 1;
        m &= m - 1;
        if ((i & 15) == wid) {
            int cnt = __shfl_sync(0xffffffffu, md.y, v);
            int off = __shfl_sync(0xffffffffu, md.x, v);
            const int* idx = g_idx + off;
            float4 acc = make_float4(0.f, 0.f, 0.f, 0.f);
            int j = 0;
            for (; j + 3 < cnt; j += 4) {
                int p0 = idx[j], p1 = idx[j+1], p2 = idx[j+2], p3 = idx[j+3];
                float4 a = __ldcs(reinterpret_cast<const float4*>(feats + (size_t)p0 * CC) + lane);
                float4 c = __ldcs(reinterpret_cast<const float4*>(feats + (size_t)p1 * CC) + lane);
                float4 e = __ldcs(reinterpret_cast<const float4*>(feats + (size_t)p2 * CC) + lane);
                float4 f = __ldcs(reinterpret_cast<const float4*>(feats + (size_t)p3 * CC) + lane);
                acc.x += a.x + c.x; acc.y += a.y + c.y;
                acc.z += a.z + c.z; acc.w += a.w + c.w;
                acc.x += e.x + f.x; acc.y += e.y + f.y;
                acc.z += e.z + f.z; acc.w += e.w + f.w;
            }
            for (; j < cnt; j++) {
                float4 a = __ldcs(reinterpret_cast<const float4*>(feats + (size_t)idx[j] * CC) + lane);
                acc.x += a.x; acc.y += a.y; acc.z += a.z; acc.w += a.w;
            }
            *reinterpret_cast<float4*>(&tile[v][lane * 4]) = acc;
        }
        i++;
    }
    __syncthreads();

    // out[b][c][x][y] via float4 over 4 consecutive y (NYY%4==0; ragged tail is
    // quad-aligned: 200 = 6*32 + 8). Warp: c = t>>3 (4 channels), yq = t&7.
    #pragma unroll
    for (int k = 0; k < 2; k++) {
        int task = tid + k * 512;       // 0..1023
        int c  = task >> 3;             // 0..127
        int yq = task & 7;              // 0..7
        int y0 = ybase + yq * 4;
        if (y0 < NYY) {
            float4 vv;
            vv.x = tile[yq*4 + 0][c];
            vv.y = tile[yq*4 + 1][c];
            vv.z = tile[yq*4 + 2][c];
            vv.w = tile[yq*4 + 3][c];
            __stcs(reinterpret_cast<float4*>(&out[((size_t)(b * CC + c) * NXX + x) * NYY + y0]), vv);
        }
    }
}

// ---------------- launch ----------------
extern "C" void kernel_launch(void* const* d_in, const int* in_sizes, int n_in,
                              void* d_out, int out_size) {
    const float* cam_feats  = (const float*)d_in[0];
    const float* rots       = (const float*)d_in[1];
    const float* trans      = (const float*)d_in[2];
    const float* intrins    = (const float*)d_in[3];
    const float* post_rots  = (const float*)d_in[4];
    const float* post_trans = (const float*)d_in[5];
    float* out = (float*)d_out;

    k_geom<<<(NPTS + 255) / 256, 256>>>(rots, trans, intrins, post_rots, post_trans);
    k_scan1<<<NSCAN_BLOCKS, 256>>>();
    k_fill<<<(NPTS + 255) / 256, 256>>>();

    dim3 ggrid((NYY + 31) / 32, NXX, BV);
    k_gather<<<ggrid, 512>>>(cam_feats, out);
}

// round 14
// speedup vs baseline: 3.5422x; 1.3188x over previous
#include <cuda_runtime.h>

// ---------------- problem constants ----------------
#define BV    4      // batch
#define NCAM  6      // cameras
#define DDEP  41     // depth bins
#define FHH   8      // feature H
#define FWW   22     // feature W
#define CC    128    // channels
#define NXX   200
#define NYY   200
#define NPTS  (BV*NCAM*DDEP*FHH*FWW)   // 173184
#define NVOX  (NXX*NYY*BV)             // 160000 (divisible by 4)

#define SCAN_BLOCK   1024
#define NSCAN_BLOCKS ((NVOX + SCAN_BLOCK - 1) / SCAN_BLOCK) // 157

// ---------------- static scratch (no allocations allowed) ----------------
// Replay invariants at kernel_launch entry: g_count == 0, g_alloc == 0.
__device__ __align__(16) int  g_count[NVOX];   // points per voxel (transient)
__device__ __align__(16) int2 g_meta[NVOX];    // {final CSR offset, count} (RO in gather)
__device__ int   g_alloc;                      // CSR allocation cursor
__device__ int   g_pvox[NPTS];                 // voxel id per point (-1 dropped)
__device__ int   g_prank[NPTS];                // rank of point within its voxel
__device__ int   g_idx[NPTS];                  // CSR point indices

// strict separately-rounded dot-3 (FROZEN — matches reference bit-exactly)
__device__ __forceinline__ float dot3_strict(float a0, float a1, float a2,
                                             float b0, float b1, float b2) {
    float p0 = __fmul_rn(a0, b0);
    float p1 = __fmul_rn(a1, b1);
    float p2 = __fmul_rn(a2, b2);
    return __fadd_rn(__fadd_rn(p0, p1), p2);
}

// ---------------- 3x3 inverse (FROZEN — R6/R7 verified) ----------------
__device__ void inv3_lu(const float* __restrict__ A, float* __restrict__ X) {
    float a[3][3];
    #pragma unroll
    for (int r = 0; r < 3; r++)
        #pragma unroll
        for (int c = 0; c < 3; c++)
            a[r][c] = A[r*3+c];
    int piv[3] = {0, 1, 2};
    {
        int p = 0;
        float m = fabsf(a[0][0]);
        if (fabsf(a[1][0]) > m) { m = fabsf(a[1][0]); p = 1; }
        if (fabsf(a[2][0]) > m) { p = 2; }
        if (p != 0) {
            #pragma unroll
            for (int c = 0; c < 3; c++) { float t = a[0][c]; a[0][c] = a[p][c]; a[p][c] = t; }
            int t = piv[0]; piv[0] = piv[p]; piv[p] = t;
        }
        float rcp = 1.0f / a[0][0];
        float l10 = __fmul_rn(a[1][0], rcp);
        float l20 = __fmul_rn(a[2][0], rcp);
        a[1][1] = fmaf(-l10, a[0][1], a[1][1]);
        a[1][2] = fmaf(-l10, a[0][2], a[1][2]);
        a[2][1] = fmaf(-l20, a[0][1], a[2][1]);
        a[2][2] = fmaf(-l20, a[0][2], a[2][2]);
        a[1][0] = l10; a[2][0] = l20;
    }
    {
        if (fabsf(a[2][1]) > fabsf(a[1][1])) {
            #pragma unroll
            for (int c = 0; c < 3; c++) { float t = a[1][c]; a[1][c] = a[2][c]; a[2][c] = t; }
            int t = piv[1]; piv[1] = piv[2]; piv[2] = t;
        }
        float rcp = 1.0f / a[1][1];
        float l21 = __fmul_rn(a[2][1], rcp);
        a[2][2] = fmaf(-l21, a[1][2], a[2][2]);
        a[2][1] = l21;
    }
    float r00 = 1.0f / a[0][0];
    float r11 = 1.0f / a[1][1];
    float r22 = 1.0f / a[2][2];
    #pragma unroll
    for (int c = 0; c < 3; c++) {
        float b0 = (piv[0] == c) ? 1.0f : 0.0f;
        float b1 = (piv[1] == c) ? 1.0f : 0.0f;
        float b2 = (piv[2] == c) ? 1.0f : 0.0f;
        float y0 = b0;
        float y1 = fmaf(-a[1][0], y0, b1);
        float y2 = fmaf(-a[2][1], y1, fmaf(-a[2][0], y0, b2));
        float x2 = __fmul_rn(y2, r22);
        float x1 = __fmul_rn(fmaf(-a[1][2], x2, y1), r11);
        float x0 = __fmul_rn(fmaf(-a[0][1], x1, fmaf(-a[0][2], x2, y0)), r00);
        X[0*3+c] = x0; X[1*3+c] = x1; X[2*3+c] = x2;
    }
}

// ---------------- K0: geometry (FROZEN) + count/rank; cams folded in-block ----
__global__ __launch_bounds__(256) void k_geom(const float* __restrict__ rots,
                                              const float* __restrict__ trans,
                                              const float* __restrict__ intrins,
                                              const float* __restrict__ post_rots,
                                              const float* __restrict__ post_trans) {
    __shared__ float scam[BV*NCAM][24];
    int tid = threadIdx.x;
    if (tid < BV*NCAM) {
        int c = tid;
        float P[9], Ki[9];
        inv3_lu(post_rots + c*9, P);
        inv3_lu(intrins  + c*9, Ki);
        const float* R  = rots + c*9;
        float* cm = scam[c];
        #pragma unroll
        for (int r = 0; r < 9; r++) cm[r] = P[r];
        #pragma unroll
        for (int r = 0; r < 3; r++) cm[9+r] = post_trans[c*3+r];
        #pragma unroll
        for (int r = 0; r < 3; r++)
            #pragma unroll
            for (int cc2 = 0; cc2 < 3; cc2++)
                cm[12 + r*3 + cc2] = dot3_strict(R[r*3+0], R[r*3+1], R[r*3+2],
                                                 Ki[0*3+cc2], Ki[1*3+cc2], Ki[2*3+cc2]);
        #pragma unroll
        for (int r = 0; r < 3; r++) cm[21+r] = trans[c*3+r];
    }
    __syncthreads();

    int p = blockIdx.x * blockDim.x + tid;
    if (p >= NPTS) return;

    int w = p % FWW;
    int t = p / FWW;
    int h = t % FHH;  t /= FHH;
    int d = t % DDEP;
    int cam = t / DDEP;            // b*NCAM + n
    int b   = cam / NCAM;

    // linspace WITHOUT endpoint fixup (verified bit-exact in R7)
    const float stepx = 351.0f / 21.0f;
    const float stepy = 127.0f / 7.0f;
    float fx = __fmul_rn((float)w, stepx);
    float fy = __fmul_rn((float)h, stepy);
    float fd = 4.0f + (float)d;

    const float* cm = scam[cam];

    float s0 = __fadd_rn(fx, -cm[9]);
    float s1 = __fadd_rn(fy, -cm[10]);
    float s2 = __fadd_rn(fd, -cm[11]);

    float p2x = dot3_strict(cm[0], cm[1], cm[2], s0, s1, s2);
    float p2y = dot3_strict(cm[3], cm[4], cm[5], s0, s1, s2);
    float p2z = dot3_strict(cm[6], cm[7], cm[8], s0, s1, s2);

    float p3x = __fmul_rn(p2x, p2z);
    float p3y = __fmul_rn(p2y, p2z);
    float p3z = p2z;

    float ex = __fadd_rn(dot3_strict(cm[12], cm[13], cm[14], p3x, p3y, p3z), cm[21]);
    float ey = __fadd_rn(dot3_strict(cm[15], cm[16], cm[17], p3x, p3y, p3z), cm[22]);
    float ez = __fadd_rn(dot3_strict(cm[18], cm[19], cm[20], p3x, p3y, p3z), cm[23]);

    float vx = __fadd_rn(ex, 50.0f) / 0.5f;
    float vy = __fadd_rn(ey, 50.0f) / 0.5f;
    float vz = __fdiv_rn(__fadd_rn(ez, 10.0f), 20.0f);
    int gx = (int)vx;
    int gy = (int)vy;
    int gz = (int)vz;

    int vox = -1, rank = 0;
    if (gx >= 0 && gx < NXX && gy >= 0 && gy < NYY && gz == 0) {
        vox = (gx * NYY + gy) * BV + b;
        rank = atomicAdd(&g_count[vox], 1);
    }
    g_pvox[p]  = vox;
    g_prank[p] = rank;
}

// ---------------- K1: block scan + atomic base; emit {off,cnt}; zero g_count --
__global__ __launch_bounds__(256) void k_scan1() {
    __shared__ int wsum[8];
    __shared__ int sbase;
    int bb = blockIdx.x, t = threadIdx.x;
    int lane = t & 31, wid = t >> 5;
    int base = bb * SCAN_BLOCK + t * 4;   // NVOX%4==0: int4-clean

    int4 q = make_int4(0, 0, 0, 0);
    if (base < NVOX) q = *reinterpret_cast<const int4*>(&g_count[base]);
    int s = q.x + q.y + q.z + q.w;

    int incl = s;
    #pragma unroll
    for (int o = 1; o < 32; o <<= 1) {
        int x = __shfl_up_sync(0xffffffffu, incl, o);
        if (lane >= o) incl += x;
    }
    if (lane == 31) wsum[wid] = incl;
    __syncthreads();
    if (t < 8) {
        int w = wsum[t];
        int iw = w;
        #pragma unroll
        for (int o = 1; o < 8; o <<= 1) {
            int x = __shfl_up_sync(0xffu, iw, o);
            if (t >= o) iw += x;
        }
        wsum[t] = iw - w;     // exclusive warp base
    }
    __syncthreads();

    int excl = incl - s + wsum[wid];
    if (t == 255) sbase = atomicAdd(&g_alloc, excl + s);  // block total
    __syncthreads();

    if (base < NVOX) {
        int r0 = excl + sbase;
        int r1 = r0 + q.x;
        int r2 = r1 + q.y;
        int r3 = r2 + q.z;
        int4* mp = reinterpret_cast<int4*>(&g_meta[base]);
        mp[0] = make_int4(r0, q.x, r1, q.y);
        mp[1] = make_int4(r2, q.z, r3, q.w);
        *reinterpret_cast<int4*>(&g_count[base]) = make_int4(0, 0, 0, 0); // reset
    }
}

// ---------------- K2: fill CSR index array; reset alloc cursor ----------------
__global__ void k_fill() {
    int p = blockIdx.x * blockDim.x + threadIdx.x;
    if (p == 0) g_alloc = 0;            // reset for next launch
    if (p >= NPTS) return;
    int vox = g_pvox[p];
    if (vox >= 0)
        g_idx[g_meta[vox].x + g_prank[p]] = p;
}

// ---------------- K3: dynamic warp-per-voxel gather (pure read) ---------------
// block: 512 threads (16 warps); grid (7 ytiles, NX, B).
__global__ __launch_bounds__(512) void k_gather(const float* __restrict__ feats,
                                                float* __restrict__ out) {
    __shared__ float tile[32][132];     // rows float4-aligned
    __shared__ int   s_vox[32];         // compacted occupied-lane list
    __shared__ int   s_q;               // dynamic voxel cursor
    int tid  = threadIdx.x;
    int lane = tid & 31;
    int wid  = tid >> 5;
    int ytile = blockIdx.x, x = blockIdx.y, b = blockIdx.z;
    int ybase = ytile * 32;

    // lane-parallel metadata: lane v covers y = ybase + v (same in every warp)
    int vy = ybase + lane;
    int2 md = make_int2(0, 0);
    if (vy < NYY) md = g_meta[(x * NYY + vy) * BV + b];
    unsigned mask = __ballot_sync(0xffffffffu, md.y != 0);
    int nocc = __popc(mask);

    if (nocc == 0) {
        // ---- fast path: all 32 voxels empty; stream zeros, no smem ----
        float4 z = make_float4(0.f, 0.f, 0.f, 0.f);
        #pragma unroll
        for (int k = 0; k < 2; k++) {
            int task = tid + k * 512;
            int c  = task >> 3;
            int yq = task & 7;
            int y0 = ybase + yq * 4;
            if (y0 < NYY)
                __stcs(reinterpret_cast<float4*>(&out[((size_t)(b * CC + c) * NXX + x) * NYY + y0]), z);
        }
        return;
    }

    // zero tile + compact occupied list
    {
        float4 zz = make_float4(0.f, 0.f, 0.f, 0.f);
        float4* tp = reinterpret_cast<float4*>(&tile[0][0]);
        #pragma unroll
        for (int k = 0; k < 3; k++) {
            int i = tid + k * 512;
            if (i < 32 * 33) tp[i] = zz;   // 32*132/4 = 1056
        }
    }
    if (wid == 0) {
        if (lane == 0) s_q = 0;
        if ((mask >> lane) & 1) {
            int r = __popc(mask & ((1u << lane) - 1));
            s_vox[r] = lane;
        }
    }
    __syncthreads();

    // dynamic dispatch over occupied voxels
    while (true) {
        int t;
        if (lane == 0) t = atomicAdd(&s_q, 1);
        t = __shfl_sync(0xffffffffu, t, 0);
        if (t >= nocc) break;
        int v   = s_vox[t];
        int cnt = __shfl_sync(0xffffffffu, md.y, v);
        int off = __shfl_sync(0xffffffffu, md.x, v);
        const int* idx = g_idx + off;

        float4 acc = make_float4(0.f, 0.f, 0.f, 0.f);
        for (int j0 = 0; j0 < cnt; j0 += 32) {
            int lim = min(32, cnt - j0);
            int pi = (lane < lim) ? idx[j0 + lane] : 0;   // ONE coalesced load
            int j = 0;
            for (; j + 3 < lim; j += 4) {
                int p0 = __shfl_sync(0xffffffffu, pi, j);
                int p1 = __shfl_sync(0xffffffffu, pi, j + 1);
                int p2 = __shfl_sync(0xffffffffu, pi, j + 2);
                int p3 = __shfl_sync(0xffffffffu, pi, j + 3);
                float4 a = __ldcs(reinterpret_cast<const float4*>(feats + (size_t)p0 * CC) + lane);
                float4 c = __ldcs(reinterpret_cast<const float4*>(feats + (size_t)p1 * CC) + lane);
                float4 e = __ldcs(reinterpret_cast<const float4*>(feats + (size_t)p2 * CC) + lane);
                float4 f = __ldcs(reinterpret_cast<const float4*>(feats + (size_t)p3 * CC) + lane);
                acc.x += a.x + c.x; acc.y += a.y + c.y;
                acc.z += a.z + c.z; acc.w += a.w + c.w;
                acc.x += e.x + f.x; acc.y += e.y + f.y;
                acc.z += e.z + f.z; acc.w += e.w + f.w;
            }
            for (; j < lim; j++) {
                int p0 = __shfl_sync(0xffffffffu, pi, j);
                float4 a = __ldcs(reinterpret_cast<const float4*>(feats + (size_t)p0 * CC) + lane);
                acc.x += a.x; acc.y += a.y; acc.z += a.z; acc.w += a.w;
            }
        }
        *reinterpret_cast<float4*>(&tile[v][lane * 4]) = acc;
    }
    __syncthreads();

    // out[b][c][x][y] via float4 over 4 consecutive y
    #pragma unroll
    for (int k = 0; k < 2; k++) {
        int task = tid + k * 512;       // 0..1023
        int c  = task >> 3;             // 0..127
        int yq = task & 7;              // 0..7
        int y0 = ybase + yq * 4;
        if (y0 < NYY) {
            float4 vv;
            vv.x = tile[yq*4 + 0][c];
            vv.y = tile[yq*4 + 1][c];
            vv.z = tile[yq*4 + 2][c];
            vv.w = tile[yq*4 + 3][c];
            __stcs(reinterpret_cast<float4*>(&out[((size_t)(b * CC + c) * NXX + x) * NYY + y0]), vv);
        }
    }
}

// ---------------- launch ----------------
extern "C" void kernel_launch(void* const* d_in, const int* in_sizes, int n_in,
                              void* d_out, int out_size) {
    const float* cam_feats  = (const float*)d_in[0];
    const float* rots       = (const float*)d_in[1];
    const float* trans      = (const float*)d_in[2];
    const float* intrins    = (const float*)d_in[3];
    const float* post_rots  = (const float*)d_in[4];
    const float* post_trans = (const float*)d_in[5];
    float* out = (float*)d_out;

    k_geom<<<(NPTS + 255) / 256, 256>>>(rots, trans, intrins, post_rots, post_trans);
    k_scan1<<<NSCAN_BLOCKS, 256>>>();
    k_fill<<<(NPTS + 255) / 256, 256>>>();

    dim3 ggrid((NYY + 31) / 32, NXX, BV);
    k_gather<<<ggrid, 512>>>(cam_feats, out);
}